// round 7
// baseline (speedup 1.0000x reference)
#include <cuda_runtime.h>
#include <cstdint>
#include <math.h>

#define CS     8
#define NG     192
#define PITCH  196                // floats per row: 2 guard + 192 + 2 guard
#define BROWS  26                 // rows -1..24
#define NTHR   768
#define TSTEPS 256
#define NBLK   (TSTEPS / 2)
#define BUFSZ  (BROWS * PITCH)
#define HALOSZ (2 * 2 * 3 * PITCH)   // [parity][side][idx][PITCH]
#define SMEMFLOATS (2 * BUFSZ + HALOSZ + TSTEPS + 4)

typedef unsigned long long ull;

__device__ __forceinline__ uint32_t s2u(const void* p) {
    return (uint32_t)__cvta_generic_to_shared((void*)p);
}
__device__ __forceinline__ uint32_t mapa_u32(uint32_t a, uint32_t r) {
    uint32_t d;
    asm("mapa.shared::cluster.u32 %0, %1, %2;" : "=r"(d) : "r"(a), "r"(r));
    return d;
}
__device__ __forceinline__ void st_cluster_b64(uint32_t a, ull v) {
    asm volatile("st.shared::cluster.b64 [%0], %1;" :: "r"(a), "l"(v) : "memory");
}
__device__ __forceinline__ void cl_arrive() {
    asm volatile("barrier.cluster.arrive.aligned;" ::: "memory");
}
__device__ __forceinline__ void cl_wait() {
    asm volatile("barrier.cluster.wait.aligned;" ::: "memory");
}

// ---- packed f32x2 helpers ----
__device__ __forceinline__ ull pk(float lo, float hi) {
    ull r; asm("mov.b64 %0, {%1, %2};" : "=l"(r) : "f"(lo), "f"(hi)); return r;
}
__device__ __forceinline__ void upk(ull v, float& lo, float& hi) {
    asm("mov.b64 {%0, %1}, %2;" : "=f"(lo), "=f"(hi) : "l"(v));
}
__device__ __forceinline__ ull add2(ull a, ull b) {
    ull r; asm("add.rn.f32x2 %0, %1, %2;" : "=l"(r) : "l"(a), "l"(b)); return r;
}
__device__ __forceinline__ ull mul2(ull a, ull b) {
    ull r; asm("mul.rn.f32x2 %0, %1, %2;" : "=l"(r) : "l"(a), "l"(b)); return r;
}
__device__ __forceinline__ ull fma2(ull a, ull b, ull c) {
    ull r; asm("fma.rn.f32x2 %0, %1, %2, %3;" : "=l"(r) : "l"(a), "l"(b), "l"(c)); return r;
}
__device__ __forceinline__ ull lds64(const float* p) { return *(const ull*)p; }
__device__ __forceinline__ void sts64(float* p, ull v) { *(ull*)p = v; }

__device__ __forceinline__ float pml1(int i) {
    int d;
    if (i <= 20)           d = 20 - i;
    else if (i >= NG - 21) d = i - (NG - 21);
    else return 0.0f;
    double t = (double)d * 0.05;
    double t2 = t * t;
    return (float)(3.0 * t2 * t2);
}

__global__ void __cluster_dims__(CS, 1, 1) __launch_bounds__(NTHR, 1)
wave_kernel(const float* __restrict__ x, const float* __restrict__ rho,
            float* __restrict__ out)
{
    extern __shared__ float dsm[];
    float* buf0 = dsm;                 // even-time states, rows -1..24
    float* buf1 = dsm + BUFSZ;         // odd-time states
    float* halo = dsm + 2 * BUFSZ;     // [p][side][idx][PITCH]
    float* xs   = halo + HALOSZ;
    float* pbuf = xs + TSTEPS;

    const int tid   = threadIdx.x;
    const int pcol  = tid % 96;        // pair-column index
    const int rgrp  = tid / 96;        // 0..7, rows 3*rgrp..3*rgrp+2
    const int col0  = pcol * 2;        // even column of my pair
    const int rank  = blockIdx.x % CS;
    const int batch = blockIdx.x / CS;

    for (int i = tid; i < 2 * BUFSZ + HALOSZ; i += NTHR) dsm[i] = 0.f;
    for (int i = tid; i < TSTEPS; i += NTHR) xs[i] = x[batch * TSTEPS + i];

    // ---- coefficients (scalar compute, packed storage) ----
    const float HM2 = (float)(1.0 / (2.01 * 2.01));
    auto coefS = [&](int g, int cl, float& oQp, float& oQm, float& oRc) {
        g = min(max(g, 0), NG - 1);
        float cc = rho[g * NG + cl];
        float nn = (g > 0)      ? rho[(g - 1) * NG + cl] : 0.f;
        float ss = (g < NG - 1) ? rho[(g + 1) * NG + cl] : 0.f;
        float ww = (cl > 0)     ? rho[g * NG + cl - 1]   : 0.f;
        float ee = (cl < NG-1)  ? rho[g * NG + cl + 1]   : 0.f;
        float lpf = 0.5f * cc + 0.125f * (nn + ss + ww + ee);
        float pr  = (1.0f + tanhf(100.0f * (lpf - 0.5f))) * 0.5f;
        float c   = 1.0f - 0.1f * pr;
        float bx = pml1(g), by = pml1(cl);
        float bb = sqrtf(bx * bx + by * by);
        float A1 = 1.0f / (1.0f + 0.5f * bb);
        float Q  = A1 * (1.0f - 0.5f * bb);
        float R  = A1 * (c * c) * HM2;
        oQp = 1.0f + Q - 4.0f * R; oQm = Q; oRc = R;
    };
    auto coefP = [&](int g, ull& oQp, ull& onQm, ull& oRc) {
        float q0p, q0m, r0, q1p, q1m, r1;
        coefS(g, col0, q0p, q0m, r0);
        coefS(g, col0 + 1, q1p, q1m, r1);
        oQp = pk(q0p, q1p); onQm = pk(-q0m, -q1m); oRc = pk(r0, r1);
    };
    ull Qp2[3], nQm2[3], Rc2[3], y2p[3];
#pragma unroll
    for (int k = 0; k < 3; ++k) {
        coefP(rank * 24 + rgrp * 3 + k, Qp2[k], nQm2[k], Rc2[k]);
        y2p[k] = 0ull;
    }
    const bool doUp = (rgrp == 0) && (rank > 0);
    const bool doDn = (rgrp == 7) && (rank < CS - 1);
    const bool topG = (rgrp == 0), botG = (rgrp == 7);
    ull eQp2 = 0, enQm2 = 0, eRc2 = 0;
    if (topG) coefP(rank * 24 - 1, eQp2, enQm2, eRc2);
    if (botG) coefP(rank * 24 + 24, eQp2, enQm2, eRc2);

    // halo pointers (boundary rgrps): side 0=top, 1=bottom
    const int side = botG ? 1 : 0;
    const float* h0[2]; const float* h1[2]; const float* h2[2];
#pragma unroll
    for (int p = 0; p < 2; ++p) {
        h0[p] = halo + ((p * 2 + side) * 3 + 0) * PITCH + col0 + 2;  // y(t) row ∓2
        h1[p] = halo + ((p * 2 + side) * 3 + 1) * PITCH + col0 + 2;  // y(t) row ∓1
        h2[p] = halo + ((p * 2 + side) * 3 + 2) * PITCH + col0 + 2;  // y(t-1) row ∓1
    }
    uint32_t pa0[2] = {0,0}, pa1[2] = {0,0}, pa2[2] = {0,0};
    if (doUp | doDn) {
        int nr = doUp ? rank - 1 : rank + 1;
        int ts = doUp ? 1 : 0;
#pragma unroll
        for (int p = 0; p < 2; ++p) {
            pa0[p] = mapa_u32(s2u(halo + ((p * 2 + ts) * 3 + 0) * PITCH + col0 + 2), (uint32_t)nr);
            pa1[p] = mapa_u32(s2u(halo + ((p * 2 + ts) * 3 + 1) * PITCH + col0 + 2), (uint32_t)nr);
            pa2[p] = mapa_u32(s2u(halo + ((p * 2 + ts) * 3 + 2) * PITCH + col0 + 2), (uint32_t)nr);
        }
    }

    float* q0f = buf0 + (1 + 3 * rgrp) * PITCH + col0 + 2;
    float* q1f = buf1 + (1 + 3 * rgrp) * PITCH + col0 + 2;

    // Source (40,96): rank1 rgrp5 k1, pair 48 lo. Probes (160,{48,96,144}): rank6 rgrp5 k1, pairs {24,48,72} lo.
    const bool isSrc = (rank == 1) && (rgrp == 5) && (pcol == 48);
    const bool isPrb = (rank == 6) && (rgrp == 5) &&
                       ((pcol == 24) | (pcol == 48) | (pcol == 72));
    float pacc = 0.f;
    ull pub = 0ull;

    cl_arrive(); cl_wait();   // init visible cluster-wide

    // packed stencil: yn = Qp*c + (-Qm)*y2 + Rc*((n+s)+(w|c)+(c|e))
    auto cell = [&](ull n, ull c, ull s, float w, float e,
                    ull qp, ull nqm, ull rc, ull y2v) -> ull {
        float clo, chi; upk(c, clo, chi);
        ull hsum = add2(pk(w, clo), pk(chi, e));
        ull tot  = add2(add2(n, s), hsum);
        return fma2(qp, c, fma2(nqm, y2v, mul2(rc, tot)));
    };

    for (int b = 0; b < NBLK; ++b) {
        const int hp = b & 1, hq = hp ^ 1;
        const float xs1 = xs[2 * b];
        const float xs2 = xs[2 * b + 1];

        // ============ step 1: t -> t+1 (read buf0 + halos, write buf1) ============
        {
            ull n, c;
            if (topG) {
                // ext row -1 first
                ull hn = lds64(h0[hp]);     // y(t) row -2
                ull hc = lds64(h1[hp]);     // y(t) row -1
                ull hy = lds64(h2[hp]);     // y(t-1) row -1
                float hw = h1[hp][-1], he = h1[hp][2];
                ull ye = cell(hn, hc, lds64(q0f), hw, he, eQp2, enQm2, eRc2, hy);
                sts64(q1f - PITCH, ye);
                n = hc;
            } else {
                n = lds64(q0f - PITCH);
            }
            c = lds64(q0f);
#pragma unroll
            for (int k = 0; k < 3; ++k) {
                ull s;
                if (botG && k == 2) s = lds64(h1[hp]);         // y(t) row 24
                else                s = lds64(q0f + (k + 1) * PITCH);
                float w = q0f[k * PITCH - 1], e = q0f[k * PITCH + 2];
                ull yn = cell(n, c, s, w, e, Qp2[k], nQm2[k], Rc2[k], y2p[k]);
                if (k == 1) {
                    if (isSrc) { float lo, hi; upk(yn, lo, hi); yn = pk(lo + xs1, hi); }
                    if (isPrb) { float lo, hi; upk(yn, lo, hi); pacc = fmaf(lo, lo, pacc); }
                }
                sts64(q1f + k * PITCH, yn);
                if (topG && k == 0) pub = yn;
                if (botG && k == 2) pub = yn;
                y2p[k] = c; n = c; c = s;
            }
            if (botG) {
                // ext row 24: n = y(t) row 23 (= y2p[2]), c = y(t) row 24, s = y(t) row 25
                ull hc = lds64(h1[hp]);
                ull hs = lds64(h0[hp]);
                ull hy = lds64(h2[hp]);
                float hw = h1[hp][-1], he = h1[hp][2];
                ull ye = cell(y2p[2], hc, hs, hw, he, eQp2, enQm2, eRc2, hy);
                sts64(q1f + 3 * PITCH, ye);
            }
        }
        __syncthreads();   // y(t+1) rows -1..24 visible intra-CTA

        // ============ step 2: t+1 -> t+2 (read buf1, write buf0) ============
        if (!botG) {
            // forward rolling: rows k=0,1 -> arrive -> k=2
            ull n = lds64(q1f - PITCH);
            ull c = lds64(q1f);
            ull yn0 = 0, yn1 = 0;
#pragma unroll
            for (int k = 0; k < 2; ++k) {
                ull s = lds64(q1f + (k + 1) * PITCH);
                float w = q1f[k * PITCH - 1], e = q1f[k * PITCH + 2];
                ull yn = cell(n, c, s, w, e, Qp2[k], nQm2[k], Rc2[k], y2p[k]);
                if (k == 1) {
                    if (isSrc) { float lo, hi; upk(yn, lo, hi); yn = pk(lo + xs2, hi); }
                    if (isPrb) { float lo, hi; upk(yn, lo, hi); pacc = fmaf(lo, lo, pacc); }
                }
                sts64(q0f + k * PITCH, yn);
                if (k == 0) yn0 = yn; else yn1 = yn;
                y2p[k] = c; n = c; c = s;
            }
            if (doUp) {
                st_cluster_b64(pa1[hq], yn0);   // y(t+2) row 0  -> nbr y(t) row 24
                st_cluster_b64(pa0[hq], yn1);   // y(t+2) row 1  -> nbr y(t) row 25
                st_cluster_b64(pa2[hq], pub);   // y(t+1) row 0  -> nbr y(t-1) row 24
            }
            cl_arrive();
            {
                ull s = lds64(q1f + 3 * PITCH);
                float w = q1f[2 * PITCH - 1], e = q1f[2 * PITCH + 2];
                ull yn = cell(n, c, s, w, e, Qp2[2], nQm2[2], Rc2[2], y2p[2]);
                sts64(q0f + 2 * PITCH, yn);
                y2p[2] = c;
            }
        } else {
            // reverse rolling: rows k=2,1 -> push+arrive -> k=0
            ull s = lds64(q1f + 3 * PITCH);   // row 24 (ext, written in step 1)
            ull c = lds64(q1f + 2 * PITCH);
            ull yn2 = 0, yn1 = 0;
#pragma unroll
            for (int k = 2; k >= 1; --k) {
                ull n = lds64(q1f + (k - 1) * PITCH);
                float w = q1f[k * PITCH - 1], e = q1f[k * PITCH + 2];
                ull yn = cell(n, c, s, w, e, Qp2[k], nQm2[k], Rc2[k], y2p[k]);
                sts64(q0f + k * PITCH, yn);
                if (k == 2) yn2 = yn; else yn1 = yn;
                y2p[k] = c; s = c; c = n;
            }
            if (doDn) {
                st_cluster_b64(pa1[hq], yn2);   // y(t+2) row 23 -> nbr y(t) row -1
                st_cluster_b64(pa0[hq], yn1);   // y(t+2) row 22 -> nbr y(t) row -2
                st_cluster_b64(pa2[hq], pub);   // y(t+1) row 23 -> nbr y(t-1) row -1
            }
            cl_arrive();
            {
                ull n = lds64(q1f - PITCH);
                float w = q1f[-1], e = q1f[2];
                ull yn = cell(n, c, s, w, e, Qp2[0], nQm2[0], Rc2[0], y2p[0]);
                sts64(q0f, yn);
                y2p[0] = c;
            }
        }
        __syncthreads();   // y(t+2) visible intra-CTA before next block
        cl_wait();         // neighbors' halo pushes visible
    }

    if (isPrb) pbuf[(col0 - 48) / 48] = pacc;
    __syncthreads();
    if (rank == 6 && tid == 0) {
        float a = pbuf[0], b = pbuf[1], c = pbuf[2];
        float s = a + b + c;
        out[batch * 3 + 0] = a / s;
        out[batch * 3 + 1] = b / s;
        out[batch * 3 + 2] = c / s;
    }
}

extern "C" void kernel_launch(void* const* d_in, const int* in_sizes, int n_in,
                              void* d_out, int out_size)
{
    (void)in_sizes; (void)n_in; (void)out_size;
    const float* x   = (const float*)d_in[0];   // (4,256) f32
    const float* rho = (const float*)d_in[1];   // (192,192) f32
    float* out = (float*)d_out;                 // (4,3) f32
    cudaFuncSetAttribute(wave_kernel,
                         cudaFuncAttributeMaxDynamicSharedMemorySize,
                         SMEMFLOATS * (int)sizeof(float));
    wave_kernel<<<dim3(CS * 4), dim3(NTHR), SMEMFLOATS * sizeof(float)>>>(x, rho, out);
}